// round 8
// baseline (speedup 1.0000x reference)
#include <cuda_runtime.h>
#include <cuda_bf16.h>
#include <cstdint>
#include <math.h>

#define DDIM   256
#define NROWS  8192
#define TMT    128            // tile M
#define TNT    128            // tile N
#define KC     128            // int8 per K-chunk (128 bytes per smem row)
#define NCHUNK (DDIM / KC)    // 2
#define TILE_B 16384          // 128 rows x 128 bytes
#define SMEM_DYN (2 * 2 * TILE_B)   // 2 stages x {A, B} = 64 KB
#define NCOLBLK 64

// ---------------- device scratch (no allocation allowed) -------------------
__device__ double g_part[NCOLBLK][DDIM];   // per-block column partial sums
__device__ float  g_sq[NROWS];             // exact fp32 squared norms
__device__ float  g_scale[NROWS];          // per-row quant scale (rowmax/127)
__device__ float  g_inv4;                  // log2(e) / (bw*16)
__device__ double g_acc;
__device__ unsigned g_tick_cs;
__device__ unsigned g_tick_mm;
__device__ int8_t g_i8[(size_t)NROWS * DDIM];

// ---------------- PTX helpers (base sm_80-class, legal on sm_103) ----------
__device__ __forceinline__ uint32_t smem_u32(const void* p) {
    uint32_t a;
    asm("{ .reg .u64 t; cvta.to.shared.u64 t, %1; cvt.u32.u64 %0, t; }"
        : "=r"(a) : "l"(p));
    return a;
}
__device__ __forceinline__ void ldsm4(uint32_t* r, uint32_t addr) {
    asm volatile("ldmatrix.sync.aligned.m8n8.x4.shared.b16 {%0,%1,%2,%3}, [%4];"
                 : "=r"(r[0]), "=r"(r[1]), "=r"(r[2]), "=r"(r[3]) : "r"(addr));
}
// s8 x s8 -> s32, m16n8k32
__device__ __forceinline__ void imma16832(int* c, const uint32_t* a,
                                          uint32_t b0, uint32_t b1) {
    asm volatile(
        "mma.sync.aligned.m16n8k32.row.col.s32.s8.s8.s32 "
        "{%0,%1,%2,%3}, {%4,%5,%6,%7}, {%8,%9}, {%0,%1,%2,%3};"
        : "+r"(c[0]), "+r"(c[1]), "+r"(c[2]), "+r"(c[3])
        : "r"(a[0]), "r"(a[1]), "r"(a[2]), "r"(a[3]), "r"(b0), "r"(b1));
}
__device__ __forceinline__ void cp16(uint32_t dst, const void* src) {
    asm volatile("cp.async.cg.shared.global [%0], [%1], 16;"
                 :: "r"(dst), "l"(__cvta_generic_to_global(src)) : "memory");
}
__device__ __forceinline__ float ex2f(float x) {
    float r;
    asm("ex2.approx.ftz.f32 %0, %1;" : "=f"(r) : "f"(x));
    return r;
}

// ---------------- prep: norms + per-row int8 quantization -------------------
__global__ void k_prep(const float* __restrict__ src,
                       const float* __restrict__ tgt, int n) {
    if (blockIdx.x == 0 && threadIdx.x == 0) g_tick_cs = 0u;
    int row  = blockIdx.x * 8 + (threadIdx.x >> 5);
    int lane = threadIdx.x & 31;
    const float* p = (row < n) ? (src + (size_t)row * DDIM)
                               : (tgt + (size_t)(row - n) * DDIM);
    const float4* p4 = (const float4*)p;
    float4 v0 = p4[lane];
    float4 v1 = p4[lane + 32];
    float s = v0.x * v0.x + v0.y * v0.y + v0.z * v0.z + v0.w * v0.w
            + v1.x * v1.x + v1.y * v1.y + v1.z * v1.z + v1.w * v1.w;
    float m = fmaxf(fmaxf(fmaxf(fabsf(v0.x), fabsf(v0.y)),
                          fmaxf(fabsf(v0.z), fabsf(v0.w))),
                    fmaxf(fmaxf(fabsf(v1.x), fabsf(v1.y)),
                          fmaxf(fabsf(v1.z), fabsf(v1.w))));
#pragma unroll
    for (int o = 16; o; o >>= 1) {
        s += __shfl_xor_sync(0xffffffffu, s, o);
        m = fmaxf(m, __shfl_xor_sync(0xffffffffu, m, o));
    }
    float scale = m * (1.0f / 127.0f);
    float inv_s = (m > 0.f) ? (127.0f / m) : 0.f;
    // quantize 8 values -> 2 packed uint32
    int q0 = __float2int_rn(v0.x * inv_s), q1 = __float2int_rn(v0.y * inv_s);
    int q2 = __float2int_rn(v0.z * inv_s), q3 = __float2int_rn(v0.w * inv_s);
    int q4 = __float2int_rn(v1.x * inv_s), q5 = __float2int_rn(v1.y * inv_s);
    int q6 = __float2int_rn(v1.z * inv_s), q7 = __float2int_rn(v1.w * inv_s);
    uint32_t w0 = (uint32_t)(q0 & 0xFF) | ((uint32_t)(q1 & 0xFF) << 8) |
                  ((uint32_t)(q2 & 0xFF) << 16) | ((uint32_t)(q3 & 0xFF) << 24);
    uint32_t w1 = (uint32_t)(q4 & 0xFF) | ((uint32_t)(q5 & 0xFF) << 8) |
                  ((uint32_t)(q6 & 0xFF) << 16) | ((uint32_t)(q7 & 0xFF) << 24);
    uint32_t* dst = (uint32_t*)(g_i8 + (size_t)row * DDIM);
    dst[lane]      = w0;
    dst[lane + 32] = w1;
    if (lane == 0) {
        g_sq[row]    = s;
        g_scale[row] = scale;
    }
}

// ---------------- colsum partials + (last block) bandwidth ------------------
// sum(L2) = 2*N*S - 2*||colsum||^2 ; bw = sum/(N^2-N)/4 ; inv4 = log2e/(bw*16)
__global__ void k_colsum(const float* __restrict__ src,
                         const float* __restrict__ tgt, int n) {
    __shared__ double sh[DDIM];
    __shared__ bool s_last;
    int col = threadIdx.x;
    int r0  = blockIdx.x * 128;
    double s = 0.0;
    for (int r = r0; r < r0 + 128; ++r) {
        const float* p = (r < n) ? (src + (size_t)r * DDIM)
                                 : (tgt + (size_t)(r - n) * DDIM);
        s += (double)p[col];
    }
    g_part[blockIdx.x][col] = s;
    __threadfence();
    __syncthreads();
    if (col == 0)
        s_last = (atomicAdd(&g_tick_cs, 1u) == (unsigned)(gridDim.x - 1));
    __syncthreads();
    if (!s_last) return;

    double cs = 0.0;
#pragma unroll
    for (int b = 0; b < NCOLBLK; ++b) cs += g_part[b][col];
    sh[col] = cs * cs;
    __syncthreads();
    for (int o = DDIM / 2; o; o >>= 1) {
        if (col < o) sh[col] += sh[col + o];
        __syncthreads();
    }
    double csq = sh[0];
    __syncthreads();
    double Sp = 0.0;
#pragma unroll
    for (int k = 0; k < NROWS / DDIM; ++k) Sp += (double)g_sq[col + k * DDIM];
    sh[col] = Sp;
    __syncthreads();
    for (int o = DDIM / 2; o; o >>= 1) {
        if (col < o) sh[col] += sh[col + o];
        __syncthreads();
    }
    if (col == 0) {
        double N = 2.0 * (double)n;
        double sumL2 = 2.0 * N * sh[0] - 2.0 * csq;
        double bw = sumL2 / (N * N - N) / 4.0;
        g_inv4 = (float)(1.4426950408889634 / (bw * 16.0));
        g_acc = 0.0;
        g_tick_mm = 0u;
    }
}

// ---------------- main fused IMMA kernel -------------------------------------
// Smem tile: 128 rows x 128B (=128 int8 K-values), granule g at g ^ (row & 7).
__device__ __forceinline__ void copy_chunk(int c, uint32_t sbuf,
                                           int row0, int col0, int tid) {
    int bases[2] = { row0, col0 };
#pragma unroll
    for (int t = 0; t < 2; ++t) {
        int R0 = bases[t];
        uint32_t tb = sbuf + t * TILE_B;
#pragma unroll
        for (int i = 0; i < 4; ++i) {
            int idx  = i * 256 + tid;      // 0..1023 granules of 16B
            int r    = idx >> 3;
            int gcol = idx & 7;
            const void* gp = g_i8 + (size_t)(R0 + r) * DDIM + c * KC + gcol * 16;
            uint32_t soff = tb + r * 128 + (((uint32_t)(gcol ^ (r & 7))) << 4);
            cp16(soff, gp);
        }
    }
}

// 128B chunk = 4 k-steps of 32 int8 (32B = two 16B granules), same ldmatrix
// pattern as bf16 k16 (raw 16-bit granule view).
__device__ __forceinline__ void compute_chunk(
    uint32_t sbuf, int acc[2][8][4],
    const uint32_t aRow[2], const uint32_t bRow[4], int rs, int gb) {
#pragma unroll
    for (int ks = 0; ks < 4; ++ks) {
        int g = ks * 2 + gb;
        uint32_t swz = (uint32_t)(g ^ rs) << 4;
        uint32_t A[2][4], Bm[4][4];
#pragma unroll
        for (int mi = 0; mi < 2; ++mi)
            ldsm4(A[mi], sbuf + 0 * TILE_B + aRow[mi] + swz);
#pragma unroll
        for (int q = 0; q < 4; ++q)
            ldsm4(Bm[q], sbuf + 1 * TILE_B + bRow[q] + swz);
#pragma unroll
        for (int mi = 0; mi < 2; ++mi)
#pragma unroll
            for (int q = 0; q < 4; ++q) {
                imma16832(acc[mi][2 * q + 0], A[mi], Bm[q][0], Bm[q][2]);
                imma16832(acc[mi][2 * q + 1], A[mi], Bm[q][1], Bm[q][3]);
            }
    }
}

__global__ void __launch_bounds__(256, 2)
k_main(int n, float* out) {
    extern __shared__ __align__(128) char smem[];
    uint32_t sb = smem_u32(smem);
    __shared__ float s_sqi[128], s_sqj[128], s_si[128], s_sj[128], red[256];

    const int tid  = threadIdx.x;
    const int lane = tid & 31;
    const int w    = tid >> 5;
    const int wm   = w & 3;        // 4 row groups of 32
    const int wn   = w >> 2;       // 2 col groups of 64
    const int gid  = lane >> 2;
    const int tig  = lane & 3;
    const int l16  = lane & 15;
    const int gb   = lane >> 4;
    const int rs   = l16 & 7;
    const float inv4 = g_inv4;

    // triangle decode
    int L  = blockIdx.x;
    int tj = (int)((sqrtf(8.0f * (float)L + 1.0f) - 1.0f) * 0.5f);
    while ((tj + 1) * (tj + 2) / 2 <= L) ++tj;
    while (tj * (tj + 1) / 2 > L) --tj;
    int ti = L - tj * (tj + 1) / 2;
    const int row0 = ti * TMT;
    const int col0 = tj * TNT;

    if (tid < 128) {
        s_sqi[tid] = g_sq[row0 + tid];
        s_sqj[tid] = g_sq[col0 + tid];
        s_si[tid]  = g_scale[row0 + tid];
        s_sj[tid]  = g_scale[col0 + tid];
    }

    uint32_t aRow[2], bRow[4];
#pragma unroll
    for (int mi = 0; mi < 2; ++mi)
        aRow[mi] = (uint32_t)(wm * 32 + mi * 16 + l16) * 128u;
#pragma unroll
    for (int q = 0; q < 4; ++q)
        bRow[q] = (uint32_t)(wn * 64 + q * 16 + l16) * 128u;

    int acc[2][8][4];
#pragma unroll
    for (int mi = 0; mi < 2; ++mi)
#pragma unroll
        for (int nj = 0; nj < 8; ++nj)
#pragma unroll
            for (int e = 0; e < 4; ++e) acc[mi][nj][e] = 0;

    copy_chunk(0, sb, row0, col0, tid);
    asm volatile("cp.async.commit_group;" ::: "memory");

#pragma unroll
    for (int c = 0; c < NCHUNK; ++c) {
        if (c + 1 < NCHUNK) {
            copy_chunk(c + 1, sb + ((c + 1) & 1) * (2 * TILE_B), row0, col0, tid);
            asm volatile("cp.async.commit_group;" ::: "memory");
            asm volatile("cp.async.wait_group 1;" ::: "memory");
        } else {
            asm volatile("cp.async.wait_group 0;" ::: "memory");
        }
        __syncthreads();
        compute_chunk(sb + (c & 1) * (2 * TILE_B), acc, aRow, bRow, rs, gb);
        __syncthreads();
    }

    // ---- epilogue: l2 = sqi + sqj - 2*si*sj*dot_int ----
    float sqi_r[4], si_r[4];
#pragma unroll
    for (int h = 0; h < 4; ++h) {
        int rr = wm * 32 + gid + h * 8;
        sqi_r[h] = s_sqi[rr];
        si_r[h]  = 2.0f * s_si[rr];
    }

    float tsum = 0.f;
#pragma unroll
    for (int mi = 0; mi < 2; ++mi) {
#pragma unroll
        for (int nj = 0; nj < 8; ++nj) {
            int cb = wn * 64 + nj * 8 + tig * 2;
            float sj0 = s_sqj[cb], sj1 = s_sqj[cb + 1];
            float sc0 = s_sj[cb],  sc1 = s_sj[cb + 1];
#pragma unroll
            for (int e = 0; e < 4; ++e) {
                int h = mi * 2 + (e >> 1);
                float sqsum = sqi_r[h] + ((e & 1) ? sj1 : sj0);
                float csc   = si_r[h] * ((e & 1) ? sc1 : sc0);
                float d     = (float)acc[mi][nj][e];
                float l2    = fmaxf(fmaf(-csc, d, sqsum), 0.f);
                float ee = ex2f(-l2 * inv4);
                float s  = ee;         // bw*16
                ee *= ee; s += ee;     // bw*8
                ee *= ee; s += ee;     // bw*4
                ee *= ee; s += ee;     // bw*2
                ee *= ee; s += ee;     // bw
                tsum += s;
            }
        }
    }

    red[tid] = tsum;
    __syncthreads();
    if (tid < 128) red[tid] += red[tid + 128];
    __syncthreads();
    if (tid < 64) red[tid] += red[tid + 64];
    __syncthreads();
    if (tid < 32) {
        float v = red[tid] + red[tid + 32];
#pragma unroll
        for (int o = 16; o; o >>= 1) v += __shfl_xor_sync(0xffffffffu, v, o);
        if (tid == 0) {
            int half = n / TMT;
            double wgt = (ti == tj) ? 1.0
                       : (((ti < half) == (tj < half)) ? 2.0 : -2.0);
            atomicAdd(&g_acc, wgt * (double)v);
        }
    }

    // ---- last finishing block writes the final scalar ----
    if (tid == 0) {
        __threadfence();
        unsigned old = atomicAdd(&g_tick_mm, 1u);
        if (old == (unsigned)(gridDim.x - 1)) {
            double total = atomicAdd(&g_acc, 0.0);  // coherent read
            out[0] = (float)(total / ((double)n * (double)n));
        }
    }
}

// ---------------------------------------------------------------------------
extern "C" void kernel_launch(void* const* d_in, const int* in_sizes, int n_in,
                              void* d_out, int out_size) {
    const float* src = (const float*)d_in[0];
    const float* tgt = (const float*)d_in[1];
    float* out = (float*)d_out;

    int n  = in_sizes[0] / DDIM;   // 4096
    int nt = 2 * n;                // 8192

    cudaFuncSetAttribute(k_main, cudaFuncAttributeMaxDynamicSharedMemorySize,
                         SMEM_DYN);

    k_prep<<<nt / 8, 256>>>(src, tgt, n);
    k_colsum<<<nt / 128, DDIM>>>(src, tgt, n);

    int numTiles = nt / TMT;                      // 64
    int T = numTiles * (numTiles + 1) / 2;        // 2080
    k_main<<<T, 256, SMEM_DYN>>>(n, out);
}

// round 9
// speedup vs baseline: 1.7711x; 1.7711x over previous
#include <cuda_runtime.h>
#include <cuda_fp16.h>
#include <cstdint>
#include <math.h>

#define DDIM   256
#define NROWS  8192
#define TMT    128            // tile M
#define TNT    128            // tile N
#define KC     64             // fp16 per K-chunk (128 bytes per smem row)
#define NCHUNK (DDIM / KC)    // 4
#define TILE_B 16384          // 128 rows x 128 bytes
#define SMEM_DYN (2 * 2 * TILE_B)   // 2 stages x {A, B} = 64 KB
#define NCOLBLK 64

// ---------------- device scratch (no allocation allowed) -------------------
__device__ double g_part[NCOLBLK][DDIM];   // per-block column partial sums
__device__ float  g_sq[NROWS];             // exact fp32 squared norms
__device__ float  g_inv4;                  // log2(e) / (bw*16)
__device__ double g_acc;
__device__ unsigned g_tick_cs;
__device__ unsigned g_tick_mm;
__device__ __half g_h[(size_t)NROWS * DDIM];

// ---------------- PTX helpers (base sm_80-class, legal on sm_103) ----------
__device__ __forceinline__ uint32_t smem_u32(const void* p) {
    uint32_t a;
    asm("{ .reg .u64 t; cvta.to.shared.u64 t, %1; cvt.u32.u64 %0, t; }"
        : "=r"(a) : "l"(p));
    return a;
}
__device__ __forceinline__ void ldsm4(uint32_t* r, uint32_t addr) {
    asm volatile("ldmatrix.sync.aligned.m8n8.x4.shared.b16 {%0,%1,%2,%3}, [%4];"
                 : "=r"(r[0]), "=r"(r[1]), "=r"(r[2]), "=r"(r[3]) : "r"(addr));
}
// f16 x f16 -> f16 accumulate (2 regs = 4 halves per thread)
__device__ __forceinline__ void mma16816_f16(uint32_t* c, const uint32_t* a,
                                             uint32_t b0, uint32_t b1) {
    asm volatile(
        "mma.sync.aligned.m16n8k16.row.col.f16.f16.f16.f16 "
        "{%0,%1}, {%2,%3,%4,%5}, {%6,%7}, {%0,%1};"
        : "+r"(c[0]), "+r"(c[1])
        : "r"(a[0]), "r"(a[1]), "r"(a[2]), "r"(a[3]), "r"(b0), "r"(b1));
}
__device__ __forceinline__ void cp16(uint32_t dst, const void* src) {
    asm volatile("cp.async.cg.shared.global [%0], [%1], 16;"
                 :: "r"(dst), "l"(__cvta_generic_to_global(src)) : "memory");
}
__device__ __forceinline__ float ex2f(float x) {
    float r;
    asm("ex2.approx.ftz.f32 %0, %1;" : "=f"(r) : "f"(x));
    return r;
}

// ---------------- prep: squared norms (fp32 exact) + fp16 round -------------
__global__ void k_prep(const float* __restrict__ src,
                       const float* __restrict__ tgt, int n) {
    if (blockIdx.x == 0 && threadIdx.x == 0) g_tick_cs = 0u;
    int row  = blockIdx.x * 8 + (threadIdx.x >> 5);
    int lane = threadIdx.x & 31;
    const float* p = (row < n) ? (src + (size_t)row * DDIM)
                               : (tgt + (size_t)(row - n) * DDIM);
    const float4* p4 = (const float4*)p;
    float s = 0.f;
#pragma unroll
    for (int i = 0; i < 2; ++i) {
        float4 v = p4[lane + i * 32];
        s += v.x * v.x + v.y * v.y + v.z * v.z + v.w * v.w;
        __half2 h01 = __floats2half2_rn(v.x, v.y);
        __half2 h23 = __floats2half2_rn(v.z, v.w);
        size_t e0 = (size_t)row * DDIM + (lane + i * 32) * 4;
        __half2* H = (__half2*)(g_h + e0);
        H[0] = h01; H[1] = h23;
    }
#pragma unroll
    for (int o = 16; o; o >>= 1) s += __shfl_xor_sync(0xffffffffu, s, o);
    if (lane == 0) g_sq[row] = s;
}

// ---------------- colsum partials + (last block) bandwidth ------------------
// sum(L2) = 2*N*S - 2*||colsum||^2 ; bw = sum/(N^2-N)/4 ; inv4 = log2e/(bw*16)
__global__ void k_colsum(const float* __restrict__ src,
                         const float* __restrict__ tgt, int n) {
    __shared__ double sh[DDIM];
    __shared__ bool s_last;
    int col = threadIdx.x;
    int r0  = blockIdx.x * 128;
    double s = 0.0;
    for (int r = r0; r < r0 + 128; ++r) {
        const float* p = (r < n) ? (src + (size_t)r * DDIM)
                                 : (tgt + (size_t)(r - n) * DDIM);
        s += (double)p[col];
    }
    g_part[blockIdx.x][col] = s;
    __threadfence();
    __syncthreads();
    if (col == 0)
        s_last = (atomicAdd(&g_tick_cs, 1u) == (unsigned)(gridDim.x - 1));
    __syncthreads();
    if (!s_last) return;

    double cs = 0.0;
#pragma unroll
    for (int b = 0; b < NCOLBLK; ++b) cs += g_part[b][col];
    sh[col] = cs * cs;
    __syncthreads();
    for (int o = DDIM / 2; o; o >>= 1) {
        if (col < o) sh[col] += sh[col + o];
        __syncthreads();
    }
    double csq = sh[0];
    __syncthreads();
    double Sp = 0.0;
#pragma unroll
    for (int k = 0; k < NROWS / DDIM; ++k) Sp += (double)g_sq[col + k * DDIM];
    sh[col] = Sp;
    __syncthreads();
    for (int o = DDIM / 2; o; o >>= 1) {
        if (col < o) sh[col] += sh[col + o];
        __syncthreads();
    }
    if (col == 0) {
        double N = 2.0 * (double)n;
        double sumL2 = 2.0 * N * sh[0] - 2.0 * csq;
        double bw = sumL2 / (N * N - N) / 4.0;
        g_inv4 = (float)(1.4426950408889634 / (bw * 16.0));
        g_acc = 0.0;
        g_tick_mm = 0u;
    }
}

// ---------------- main fused mma.sync kernel ---------------------------------
// Smem tile layout: 128 rows x 128B, 16B granule g stored at g ^ (row & 7).
__device__ __forceinline__ void copy_chunk(int c, uint32_t sbuf,
                                           int row0, int col0, int tid) {
    int bases[2] = { row0, col0 };
#pragma unroll
    for (int t = 0; t < 2; ++t) {
        int R0 = bases[t];
        uint32_t tb = sbuf + t * TILE_B;
#pragma unroll
        for (int i = 0; i < 4; ++i) {
            int idx  = i * 256 + tid;      // 0..1023 granules
            int r    = idx >> 3;
            int gcol = idx & 7;
            const void* gp = g_h + (size_t)(R0 + r) * DDIM + c * KC + gcol * 8;
            uint32_t soff = tb + r * 128 + (((uint32_t)(gcol ^ (r & 7))) << 4);
            cp16(soff, gp);
        }
    }
}

__device__ __forceinline__ void compute_chunk(
    uint32_t sbuf, uint32_t acc[2][8][2],
    const uint32_t aRow[2], const uint32_t bRow[4], int rs, int gb) {
#pragma unroll
    for (int ks = 0; ks < 4; ++ks) {
        int g = ks * 2 + gb;
        uint32_t swz = (uint32_t)(g ^ rs) << 4;
        uint32_t A[2][4], Bm[4][4];
#pragma unroll
        for (int mi = 0; mi < 2; ++mi)
            ldsm4(A[mi], sbuf + 0 * TILE_B + aRow[mi] + swz);
#pragma unroll
        for (int q = 0; q < 4; ++q)
            ldsm4(Bm[q], sbuf + 1 * TILE_B + bRow[q] + swz);
#pragma unroll
        for (int mi = 0; mi < 2; ++mi)
#pragma unroll
            for (int q = 0; q < 4; ++q) {
                mma16816_f16(acc[mi][2 * q + 0], A[mi], Bm[q][0], Bm[q][2]);
                mma16816_f16(acc[mi][2 * q + 1], A[mi], Bm[q][1], Bm[q][3]);
            }
    }
}

__global__ void __launch_bounds__(256, 2)
k_main(int n, float* out) {
    extern __shared__ __align__(128) char smem[];
    uint32_t sb = smem_u32(smem);
    __shared__ float s_sqi[128], s_sqj[128], red[256];

    const int tid  = threadIdx.x;
    const int lane = tid & 31;
    const int w    = tid >> 5;
    const int wm   = w & 3;        // 4 row groups of 32
    const int wn   = w >> 2;       // 2 col groups of 64
    const int gid  = lane >> 2;
    const int tig  = lane & 3;
    const int l16  = lane & 15;
    const int gb   = lane >> 4;
    const int rs   = l16 & 7;
    const float inv4 = g_inv4;

    // triangle decode
    int L  = blockIdx.x;
    int tj = (int)((sqrtf(8.0f * (float)L + 1.0f) - 1.0f) * 0.5f);
    while ((tj + 1) * (tj + 2) / 2 <= L) ++tj;
    while (tj * (tj + 1) / 2 > L) --tj;
    int ti = L - tj * (tj + 1) / 2;
    const int row0 = ti * TMT;
    const int col0 = tj * TNT;

    if (tid < 128) {
        s_sqi[tid] = g_sq[row0 + tid];
        s_sqj[tid] = g_sq[col0 + tid];
    }

    uint32_t aRow[2], bRow[4];
#pragma unroll
    for (int mi = 0; mi < 2; ++mi)
        aRow[mi] = (uint32_t)(wm * 32 + mi * 16 + l16) * 128u;
#pragma unroll
    for (int q = 0; q < 4; ++q)
        bRow[q] = (uint32_t)(wn * 64 + q * 16 + l16) * 128u;

    uint32_t acc[2][8][2];
#pragma unroll
    for (int mi = 0; mi < 2; ++mi)
#pragma unroll
        for (int nj = 0; nj < 8; ++nj) {
            acc[mi][nj][0] = 0u;
            acc[mi][nj][1] = 0u;
        }

    copy_chunk(0, sb, row0, col0, tid);
    asm volatile("cp.async.commit_group;" ::: "memory");

#pragma unroll
    for (int c = 0; c < NCHUNK; ++c) {
        if (c + 1 < NCHUNK) {
            copy_chunk(c + 1, sb + ((c + 1) & 1) * (2 * TILE_B), row0, col0, tid);
            asm volatile("cp.async.commit_group;" ::: "memory");
            asm volatile("cp.async.wait_group 1;" ::: "memory");
        } else {
            asm volatile("cp.async.wait_group 0;" ::: "memory");
        }
        __syncthreads();
        compute_chunk(sb + (c & 1) * (2 * TILE_B), acc, aRow, bRow, rs, gb);
        __syncthreads();
    }

    // ---- epilogue ----
    // f16 D fragment: reg0 = (row gid,   cols tig*2, tig*2+1)
    //                 reg1 = (row gid+8, cols tig*2, tig*2+1)
    float sqi_r[4];   // rows: wm*32 + gid + {0,8,16,24}
#pragma unroll
    for (int h = 0; h < 4; ++h) sqi_r[h] = s_sqi[wm * 32 + gid + h * 8];

    float tsum = 0.f;
#pragma unroll
    for (int mi = 0; mi < 2; ++mi) {
#pragma unroll
        for (int nj = 0; nj < 8; ++nj) {
            int cb = wn * 64 + nj * 8 + tig * 2;
            float sj0 = s_sqj[cb], sj1 = s_sqj[cb + 1];
#pragma unroll
            for (int rg = 0; rg < 2; ++rg) {
                float si = sqi_r[mi * 2 + rg];
                float2 d = __half22float2(
                    *(__half2*)&acc[mi][nj][rg]);
                float l2a = fmaxf(fmaf(-2.f, d.x, si + sj0), 0.f);
                float l2b = fmaxf(fmaf(-2.f, d.y, si + sj1), 0.f);
                float ea = ex2f(-l2a * inv4);
                float eb = ex2f(-l2b * inv4);
                float sa = ea, sbv = eb;
                ea *= ea; sa += ea;  eb *= eb; sbv += eb;   // bw*8
                ea *= ea; sa += ea;  eb *= eb; sbv += eb;   // bw*4
                ea *= ea; sa += ea;  eb *= eb; sbv += eb;   // bw*2
                ea *= ea; sa += ea;  eb *= eb; sbv += eb;   // bw
                tsum += sa + sbv;
            }
        }
    }

    red[tid] = tsum;
    __syncthreads();
    if (tid < 128) red[tid] += red[tid + 128];
    __syncthreads();
    if (tid < 64) red[tid] += red[tid + 64];
    __syncthreads();
    if (tid < 32) {
        float v = red[tid] + red[tid + 32];
#pragma unroll
        for (int o = 16; o; o >>= 1) v += __shfl_xor_sync(0xffffffffu, v, o);
        if (tid == 0) {
            int half = n / TMT;
            double wgt = (ti == tj) ? 1.0
                       : (((ti < half) == (tj < half)) ? 2.0 : -2.0);
            atomicAdd(&g_acc, wgt * (double)v);
        }
    }

    // ---- last finishing block writes the final scalar ----
    if (tid == 0) {
        __threadfence();
        unsigned old = atomicAdd(&g_tick_mm, 1u);
        if (old == (unsigned)(gridDim.x - 1)) {
            double total = atomicAdd(&g_acc, 0.0);  // coherent read
            out[0] = (float)(total / ((double)n * (double)n));
        }
    }
}

// ---------------------------------------------------------------------------
extern "C" void kernel_launch(void* const* d_in, const int* in_sizes, int n_in,
                              void* d_out, int out_size) {
    const float* src = (const float*)d_in[0];
    const float* tgt = (const float*)d_in[1];
    float* out = (float*)d_out;

    int n  = in_sizes[0] / DDIM;   // 4096
    int nt = 2 * n;                // 8192

    cudaFuncSetAttribute(k_main, cudaFuncAttributeMaxDynamicSharedMemorySize,
                         SMEM_DYN);

    k_prep<<<nt / 8, 256>>>(src, tgt, n);
    k_colsum<<<nt / 128, DDIM>>>(src, tgt, n);

    int numTiles = nt / TMT;                      // 64
    int T = numTiles * (numTiles + 1) / 2;        // 2080
    k_main<<<T, 256, SMEM_DYN>>>(n, out);
}